// round 9
// baseline (speedup 1.0000x reference)
#include <cuda_runtime.h>
#include <cstdint>

// Problem constants
static constexpr int NB = 16;
static constexpr int NC = 256;
static constexpr int NH = 64;
static constexpr int NW = 64;
static constexpr int NP = 9;
static constexpr int DISP = 4;

// Tiling (R8 skeleton)
static constexpr int TI = 4;
static constexpr int CH = 8;
static constexpr int NSTAGE = NC / CH;        // 32
static constexpr int YROWS = TI + 2 * DISP;   // 12
static constexpr int PITCH = 384;
static constexpr int XAREA = CH * TI * PITCH;     // 12288
static constexpr int YAREA = CH * YROWS * PITCH;  // 36864
static constexpr int BUF = XAREA + YAREA;         // 49152
static constexpr int NTHREADS = 288;              // 9 warps, warp = di
static constexpr int NROWS = CH * YROWS + CH * TI; // 128
static constexpr int STAGE_BYTES = CH * NH * NW * 4; // 131072
static constexpr int ROWB = NW * 4;               // 256B per bulk copy
static constexpr int XSTEP = TI * PITCH;          // 1536
static constexpr int YSTEP = YROWS * PITCH;       // 4608

// smem: [0..16) mbarriers full[2]; buffers at 128
static constexpr int BUF0 = 128;
static constexpr int SMEM_TOTAL = BUF0 + 2 * BUF; // 98432 -> 2 CTAs/SM

__device__ __forceinline__ unsigned skew(int r) {
    return ((r & 1) << 4) + ((r & 2) << 5);
}
__device__ __forceinline__ void upk(unsigned long long v, float& lo, float& hi) {
    asm("mov.b64 {%0, %1}, %2;" : "=f"(lo), "=f"(hi) : "l"(v));
}
__device__ __forceinline__ unsigned long long pk(float lo, float hi) {
    unsigned long long r;
    asm("mov.b64 %0, {%1, %2};" : "=l"(r) : "f"(lo), "f"(hi));
    return r;
}
__device__ __forceinline__ void fma2(unsigned long long& acc,
                                     unsigned long long a, unsigned long long b) {
    asm("fma.rn.f32x2 %0, %1, %2, %0;" : "+l"(acc) : "l"(a), "l"(b));
}
__device__ __forceinline__ void lds2(unsigned addr,
                                     unsigned long long& a, unsigned long long& b) {
    asm volatile("ld.shared.v2.b64 {%0, %1}, [%2];"
                 : "=l"(a), "=l"(b) : "r"(addr));
}
__device__ __forceinline__ void mbar_init(unsigned addr, unsigned count) {
    asm volatile("mbarrier.init.shared.b64 [%0], %1;" :: "r"(addr), "r"(count) : "memory");
}
__device__ __forceinline__ void mbar_expect(unsigned addr, unsigned bytes) {
    asm volatile("mbarrier.arrive.expect_tx.shared.b64 _, [%0], %1;"
                 :: "r"(addr), "r"(bytes) : "memory");
}
__device__ __forceinline__ void mbar_wait(unsigned addr, unsigned parity) {
    asm volatile(
        "{\n\t"
        ".reg .pred P;\n\t"
        "WL_%=:\n\t"
        "mbarrier.try_wait.parity.acquire.cta.shared::cta.b64 P, [%0], %1, 0x989680;\n\t"
        "@P bra.uni WD_%=;\n\t"
        "bra.uni WL_%=;\n\t"
        "WD_%=:\n\t"
        "}"
        :: "r"(addr), "r"(parity) : "memory");
}
__device__ __forceinline__ void bulk_g2s(unsigned dst, const void* src,
                                         unsigned bytes, unsigned mbar) {
    asm volatile(
        "cp.async.bulk.shared::cta.global.mbarrier::complete_tx::bytes "
        "[%0], [%1], %2, [%3];"
        :: "r"(dst), "l"(src), "r"(bytes), "r"(mbar) : "memory");
}

__global__ void __launch_bounds__(NTHREADS, 2)
corr_kernel(const float* __restrict__ x, const float* __restrict__ y,
            float* __restrict__ out) {
    extern __shared__ char smem[];
    unsigned sm32;
    asm("{ .reg .u64 t; cvta.to.shared.u64 t, %1; cvt.u32.u64 %0, t; }"
        : "=r"(sm32) : "l"(smem));

    const int tid  = threadIdx.x;
    const int di   = tid >> 5;       // warp = displacement row 0..8
    const int lane = tid & 31;
    const int jg   = lane >> 2;      // 8-col group
    const int ti   = lane & 3;       // i-row in tile
    const int i0   = blockIdx.x * TI;
    const int b    = blockIdx.y;

    // Zero both buffers (halo cols / OOB rows stay zero forever).
    for (int o = tid * 16; o < 2 * BUF; o += NTHREADS * 16)
        *reinterpret_cast<float4*>(smem + BUF0 + o) = make_float4(0.f, 0.f, 0.f, 0.f);

    if (tid == 0) {
        mbar_init(sm32 + 0, 1);   // full[0]
        mbar_init(sm32 + 8, 1);   // full[1]
    }
    __syncthreads();
    asm volatile("fence.proxy.async.shared::cta;" ::: "memory");

    // Per-block valid byte count (OOB y rows are skipped, never copied).
    const int lo = (4 - i0) > 0 ? (4 - i0) : 0;
    const int hi = (i0 - 56) > 0 ? (i0 - 56) : 0;
    const unsigned BYTES = (unsigned)((CH * (YROWS - lo - hi) + CH * TI) * ROWB);

    // Row-owner precompute: thread k < 128 owns row k (one 256B bulk per stage).
    const char* src0 = nullptr;
    unsigned dsto = 0;
    bool valid = false;
    if (tid < NROWS) {
        const int k = tid;
        if (k < CH * YROWS) {
            const int cc = k / YROWS;
            const int rr = k - cc * YROWS;
            const int gy = i0 - DISP + rr;
            valid = ((unsigned)gy < (unsigned)NH);
            if (valid)
                src0 = reinterpret_cast<const char*>(
                    y + (((size_t)(b * NC + cc) * NH + gy) * NW));
            dsto = XAREA + cc * (YROWS * PITCH) + rr * PITCH + skew(rr) + 16;
        } else {
            const int j  = k - CH * YROWS;
            const int cc = j >> 2;
            const int rr = j & 3;
            valid = true;
            src0 = reinterpret_cast<const char*>(
                x + (((size_t)(b * NC + cc) * NH + (i0 + rr)) * NW));
            dsto = cc * (TI * PITCH) + rr * PITCH + skew(rr);
        }
    }

    // Prologue: register expected bytes for stages 0 and 1, then issue them.
    if (tid == 0) {
        mbar_expect(sm32 + 0, BYTES);
        mbar_expect(sm32 + 8, BYTES);
    }
    __syncthreads();   // expects registered before any completion can land
    if (valid) {
        bulk_g2s(sm32 + BUF0 + dsto, src0, ROWB, sm32 + 0);
        bulk_g2s(sm32 + BUF0 + BUF + dsto, src0 + STAGE_BYTES, ROWB, sm32 + 8);
    }

    // Accumulators (R4 layout)
    unsigned long long accE[5][4], accO[4][3];
    float sA[4], sB[4];
#pragma unroll
    for (int e = 0; e < 5; ++e)
#pragma unroll
        for (int m = 0; m < 4; ++m) accE[e][m] = 0ull;
#pragma unroll
    for (int o = 0; o < 4; ++o) {
#pragma unroll
        for (int m = 0; m < 3; ++m) accO[o][m] = 0ull;
        sA[o] = 0.f; sB[o] = 0.f;
    }

    const int r = ti + di;   // y smem row 0..11
    // Warp-staggered start channel: warp di begins its sweep at channel di&7.
    const int c0 = di & 7;
    const unsigned xoff = sm32 + BUF0 + (unsigned)(ti * PITCH) + skew(ti) + jg * 32
                        + (unsigned)(c0 * XSTEP);
    const unsigned yoff = sm32 + BUF0 + (unsigned)XAREA
                        + (unsigned)(r * PITCH) + skew(r) + jg * 32
                        + (unsigned)(c0 * YSTEP);

    for (int s = 0; s < NSTAGE; ++s) {
        const unsigned mb = sm32 + (unsigned)((s & 1) * 8);
        mbar_wait(mb, (unsigned)((s >> 1) & 1));
        if (tid == 0 && s + 2 < NSTAGE) mbar_expect(mb, BYTES);

        const unsigned bo = (unsigned)((s & 1) * BUF);

        // Incremental channel pointers with cyclic wrap (stagger by warp).
        unsigned xp = bo + xoff;
        unsigned yp = bo + yoff;

        // Prefetch X of the first channel.
        unsigned long long Xc[4];
        lds2(xp,      Xc[0], Xc[1]);
        lds2(xp + 16, Xc[2], Xc[3]);

#pragma unroll 2
        for (int t = 0; t < CH; ++t) {
            unsigned long long W[8];
            lds2(yp,      W[0], W[1]);
            lds2(yp + 16, W[2], W[3]);
            lds2(yp + 32, W[4], W[5]);
            lds2(yp + 48, W[6], W[7]);

            // Advance pointers (cyclic over 8 channels) and prefetch next X.
            unsigned xn = xp + XSTEP;
            unsigned yn = yp + YSTEP;
            if (t + c0 == CH - 1) { xn -= CH * XSTEP; yn -= CH * YSTEP; }
            unsigned long long Xn[4];
            lds2(xn,      Xn[0], Xn[1]);
            lds2(xn + 16, Xn[2], Xn[3]);

            float x0, x1, x2, x3, x4, x5, x6, x7;
            upk(Xc[0], x0, x1); upk(Xc[1], x2, x3);
            upk(Xc[2], x4, x5); upk(Xc[3], x6, x7);
            unsigned long long Sx[3] = {pk(x1, x2), pk(x3, x4), pk(x5, x6)};

#pragma unroll
            for (int e = 0; e < 5; ++e)
#pragma unroll
                for (int m = 0; m < 4; ++m)
                    fma2(accE[e][m], Xc[m], W[m + e]);

#pragma unroll
            for (int o = 0; o < 4; ++o) {
#pragma unroll
                for (int m = 0; m < 3; ++m)
                    fma2(accO[o][m], Sx[m], W[m + 1 + o]);
                float wl, wh, vl, vh;
                upk(W[o], wl, wh);
                upk(W[4 + o], vl, vh);
                sA[o] = fmaf(x0, wh, sA[o]);
                sB[o] = fmaf(x7, vl, sB[o]);
            }

            xp = xn; yp = yn;
#pragma unroll
            for (int m = 0; m < 4; ++m) Xc[m] = Xn[m];
        }

        __syncthreads();   // everyone finished reading buffer (s&1)
        if (valid && s + 2 < NSTAGE) {
            bulk_g2s(sm32 + BUF0 + (unsigned)((s & 1) * BUF) + dsto,
                     src0 + (size_t)(s + 2) * STAGE_BYTES, ROWB, mb);
        }
    }

    // ---- epilogue: scale by 1/C and store ----
    const float sc = 1.0f / (float)NC;
    float* obase = out + (((size_t)b * (NP * NP) + (size_t)di * NP) * NH
                          + (i0 + ti)) * NW + jg * 8;
#pragma unroll
    for (int e = 0; e < 5; ++e) {
        float* op = obase + (size_t)(2 * e) * NH * NW;
        float4 v;
        upk(accE[e][0], v.x, v.y); upk(accE[e][1], v.z, v.w);
        v.x *= sc; v.y *= sc; v.z *= sc; v.w *= sc;
        *reinterpret_cast<float4*>(op) = v;
        upk(accE[e][2], v.x, v.y); upk(accE[e][3], v.z, v.w);
        v.x *= sc; v.y *= sc; v.z *= sc; v.w *= sc;
        *reinterpret_cast<float4*>(op + 4) = v;
    }
#pragma unroll
    for (int o = 0; o < 4; ++o) {
        float* op = obase + (size_t)(2 * o + 1) * NH * NW;
        float f1, f2, f3, f4, f5, f6;
        upk(accO[o][0], f1, f2);
        upk(accO[o][1], f3, f4);
        upk(accO[o][2], f5, f6);
        float4 v;
        v.x = sA[o] * sc; v.y = f1 * sc; v.z = f2 * sc; v.w = f3 * sc;
        *reinterpret_cast<float4*>(op) = v;
        v.x = f4 * sc; v.y = f5 * sc; v.z = f6 * sc; v.w = sB[o] * sc;
        *reinterpret_cast<float4*>(op + 4) = v;
    }
}

extern "C" void kernel_launch(void* const* d_in, const int* in_sizes, int n_in,
                              void* d_out, int out_size) {
    const float* x = (const float*)d_in[0];
    const float* y = (const float*)d_in[1];
    float* out = (float*)d_out;
    (void)in_sizes; (void)n_in; (void)out_size;

    cudaFuncSetAttribute(corr_kernel,
                         cudaFuncAttributeMaxDynamicSharedMemorySize, SMEM_TOTAL);

    dim3 grid(NH / TI, NB);   // (16, 16) = 256 blocks
    corr_kernel<<<grid, NTHREADS, SMEM_TOTAL>>>(x, y, out);
}